// round 7
// baseline (speedup 1.0000x reference)
#include <cuda_runtime.h>
#include <cuda_bf16.h>
#include <cstdint>

// ---------------------------------------------------------------------------
// CrossAttention: B=8, Nt=1024, N=1024, D=768, H=8, HD=96, CLS=20, L=1044
// mma.sync bf16 hi/lo split. Operands pre-split (k-contiguous), cp.async
// double-buffered GEMM, threefry bitmask fused into the first two GEMMs,
// attention pass A hi-only, attention epilogue emits split bf16 directly.
// ---------------------------------------------------------------------------

#define DEV_INLINE __device__ __forceinline__

constexpr int   Bsz  = 8;
constexpr int   NtQ  = 1024;
constexpr int   Dm   = 768;
constexpr float QSCALE = 0.10206207261596577f;   // 96^-0.5

// ---------------- scratch (static device globals; no allocation) -----------
__device__ float    g_q  [Bsz * NtQ * Dm];          // 25 MB
__device__ float    g_kv [Bsz * NtQ * 2 * Dm];      // 50 MB
// pre-split GEMM operands (bf16x2 words, k-contiguous)
__device__ uint32_t g_a1h[8192 * 384], g_a1l[8192 * 384];   // query / attn-out
__device__ uint32_t g_a2h[8192 * 384], g_a2l[8192 * 384];   // key
__device__ uint32_t g_wqh [ 768 * 384], g_wql [ 768 * 384];
__device__ uint32_t g_wkvh[1536 * 384], g_wkvl[1536 * 384];
__device__ uint32_t g_wph [ 768 * 384], g_wpl [ 768 * 384];
// attention operands (head-major)
__device__ uint32_t g_qh [64 * 1024 * 48];
__device__ uint32_t g_ql [64 * 1024 * 48];
__device__ uint32_t g_kh [64 * 1024 * 48];
__device__ uint32_t g_kl [64 * 1024 * 48];
__device__ uint32_t g_vth[64 * 96 * 512];
__device__ uint32_t g_vtl[64 * 96 * 512];
__device__ uint32_t g_mask[64 * 1024 * 32];         // 8.4 MB keep-bitmask

// ---------------------------------------------------------------------------
DEV_INLINE void split2(float x, float y, uint32_t& hi, uint32_t& lo) {
    __nv_bfloat162 h = __floats2bfloat162_rn(x, y);
    float hx = __bfloat162float(h.x), hy = __bfloat162float(h.y);
    __nv_bfloat162 l = __floats2bfloat162_rn(x - hx, y - hy);
    hi = *reinterpret_cast<uint32_t*>(&h);
    lo = *reinterpret_cast<uint32_t*>(&l);
}

DEV_INLINE void mma16816(float* d, const uint32_t* a, const uint32_t* b) {
    asm volatile(
        "mma.sync.aligned.m16n8k16.row.col.f32.bf16.bf16.f32 "
        "{%0,%1,%2,%3}, {%4,%5,%6,%7}, {%8,%9}, {%0,%1,%2,%3};"
        : "+f"(d[0]), "+f"(d[1]), "+f"(d[2]), "+f"(d[3])
        : "r"(a[0]), "r"(a[1]), "r"(a[2]), "r"(a[3]), "r"(b[0]), "r"(b[1]));
}

DEV_INLINE uint32_t smem_u32(const void* p) {
    uint32_t a;
    asm("{ .reg .u64 t; cvta.to.shared.u64 t, %1; cvt.u32.u64 %0, t; }"
        : "=r"(a) : "l"(p));
    return a;
}
DEV_INLINE void cp16(uint32_t dst, const void* src) {
    asm volatile("cp.async.cg.shared.global [%0], [%1], 16;"
                 :: "r"(dst), "l"(src));
}
DEV_INLINE void cp_commit() { asm volatile("cp.async.commit_group;"); }
template<int N> DEV_INLINE void cp_wait() {
    asm volatile("cp.async.wait_group %0;" :: "n"(N));
}

DEV_INLINE uint32_t rotl32(uint32_t x, int d) { return __funnelshift_l(x, x, d); }

// JAX threefry2x32, key (0,42), partitionable: counter (0, fi), out = x0^x1
DEV_INLINE uint32_t tf_bits(uint32_t fi) {
    const uint32_t ks1 = 42u, ks2 = 0x1BD11BF0u;
    uint32_t x0 = 0u, x1 = fi + ks1;
    x0 += x1; x1 = rotl32(x1, 13); x1 ^= x0;
    x0 += x1; x1 = rotl32(x1, 15); x1 ^= x0;
    x0 += x1; x1 = rotl32(x1, 26); x1 ^= x0;
    x0 += x1; x1 = rotl32(x1,  6); x1 ^= x0;
    x0 += ks1; x1 += ks2 + 1u;
    x0 += x1; x1 = rotl32(x1, 17); x1 ^= x0;
    x0 += x1; x1 = rotl32(x1, 29); x1 ^= x0;
    x0 += x1; x1 = rotl32(x1, 16); x1 ^= x0;
    x0 += x1; x1 = rotl32(x1, 24); x1 ^= x0;
    x0 += ks2; x1 += 2u;
    x0 += x1; x1 = rotl32(x1, 13); x1 ^= x0;
    x0 += x1; x1 = rotl32(x1, 15); x1 ^= x0;
    x0 += x1; x1 = rotl32(x1, 26); x1 ^= x0;
    x0 += x1; x1 = rotl32(x1,  6); x1 ^= x0;
    x1 += ks1 + 3u;
    x0 += x1; x1 = rotl32(x1, 17); x1 ^= x0;
    x0 += x1; x1 = rotl32(x1, 29); x1 ^= x0;
    x0 += x1; x1 = rotl32(x1, 16); x1 ^= x0;
    x0 += x1; x1 = rotl32(x1, 24); x1 ^= x0;
    x0 += ks1; x1 += ks2 + 4u;
    x0 += x1; x1 = rotl32(x1, 13); x1 ^= x0;
    x0 += x1; x1 = rotl32(x1, 15); x1 ^= x0;
    x0 += x1; x1 = rotl32(x1, 26); x1 ^= x0;
    x0 += x1; x1 = rotl32(x1,  6); x1 ^= x0;
    x0 += ks2; x1 += 5u;
    return x0 ^ x1;
}

// w = (bh*1024 + q)*32 + wi ; bit j (keep=1) for col wi*32+j
DEV_INLINE uint32_t mask_word(uint32_t w) {
    const uint32_t bh = w >> 15;
    const uint32_t rest = w & 32767u;
    const uint32_t q = rest >> 5, wi = rest & 31u;
    const uint32_t fi0 = (bh * 1044u + 20u + q) * 1024u + wi * 32u;
    uint32_t bits = 0u;
#pragma unroll 4
    for (int j = 0; j < 32; j++) {
        uint32_t b = tf_bits(fi0 + (uint32_t)j);
        bits |= ((b >> 9) >= 2516583u ? 1u : 0u) << j;
    }
    return bits;
}

// ===========================================================================
//  split kernels
// ===========================================================================
// elementwise row split: fp32 [M][K] -> bf16x2 words hi/lo [M][K/2]
__global__ __launch_bounds__(256) void rowsplit(
    const float* __restrict__ src, uint32_t* __restrict__ dh,
    uint32_t* __restrict__ dl, int nwords)
{
    const int i = blockIdx.x * 256 + threadIdx.x;
    const int w = i * 2;
    if (w < nwords) {
        float4 v = *reinterpret_cast<const float4*>(src + (size_t)w * 2);
        uint32_t h0, l0, h1, l1;
        split2(v.x, v.y, h0, l0);
        split2(v.z, v.w, h1, l1);
        dh[w] = h0; dh[w + 1] = h1;
        dl[w] = l0; dl[w + 1] = l1;
    }
}

// transpose split: W [K][N] row-major -> Wt hi/lo [N][K/2] (k-contiguous)
__global__ __launch_bounds__(256) void wsplit_t(
    const float* __restrict__ W, uint32_t* __restrict__ dh,
    uint32_t* __restrict__ dl, int K, int N)
{
    __shared__ float s[32][33];
    const int tid = threadIdx.x;
    const int kt = blockIdx.y, nt = blockIdx.x;
    const int kl = tid >> 5, nl = tid & 31;
#pragma unroll
    for (int i = 0; i < 4; i++)
        s[kl + i * 8][nl] = W[(size_t)(kt * 32 + kl + i * 8) * N + nt * 32 + nl];
    __syncthreads();
    const int n2 = tid >> 3, q = tid & 7;
    const int Kw = K >> 1;
    uint32_t h, l;
    split2(s[2 * q][n2], s[2 * q + 1][n2], h, l);
    size_t o = (size_t)(nt * 32 + n2) * Kw + kt * 16 + q;
    dh[o] = h; dl[o] = l;
    split2(s[2 * q + 16][n2], s[2 * q + 17][n2], h, l);
    dh[o + 8] = h; dl[o + 8] = l;
}

// ===========================================================================
//  cp.async double-buffered mma GEMM on pre-split operands
//  C[M,N] = A[M,K] @ Bt[N,K]^T (+bias).  K-chunk 32, CTA 128x128.
// ===========================================================================
constexpr int SSTR = 20;            // padded words per smem row
constexpr int BUFW = 4 * 128 * SSTR; // words per buffer (Ah,Al,Bh,Bl)

template<bool BIAS>
__global__ __launch_bounds__(256, 2) void gemm_v2(
    const uint32_t* __restrict__ Ah_g, const uint32_t* __restrict__ Al_g,
    const uint32_t* __restrict__ Bh_g, const uint32_t* __restrict__ Bl_g,
    const float* __restrict__ bias, float* __restrict__ C,
    int M, int N, int K,
    uint32_t mw_start, uint32_t mw_end, uint32_t mw_stride)
{
    extern __shared__ uint32_t smem[];
    const int tid  = threadIdx.x;
    const int lane = tid & 31;
    const int wid  = tid >> 5;
    const int wy   = wid >> 2;
    const int wx   = wid & 3;
    const int gq = lane >> 2, gt = lane & 3;

    const int m0 = blockIdx.y * 128;
    const int n0 = blockIdx.x * 128;
    const int Kw = K >> 1;
    const int KCH = K >> 5;         // 32-wide chunks
    const uint32_t gid =
        ((uint32_t)blockIdx.y * gridDim.x + blockIdx.x) * 256u + (uint32_t)tid;

    const int crow = tid >> 2, cseg = tid & 3;     // copy mapping (2 rows apart)
    const uint32_t sm_base = smem_u32(smem);

    // issue async copies for chunk c into buffer buf
    auto load_chunk = [&](int c, int buf) {
        uint32_t* bp = smem + buf * BUFW;
        const size_t asrc = (size_t)(m0 + crow) * Kw + c * 16 + cseg * 4;
        const size_t bsrc = (size_t)(n0 + crow) * Kw + c * 16 + cseg * 4;
        const uint32_t d0 = sm_base + (uint32_t)(buf * BUFW) * 4u;
        const uint32_t off1 = (uint32_t)(crow * SSTR + cseg * 4) * 4u;
        const uint32_t off2 = (uint32_t)((crow + 64) * SSTR + cseg * 4) * 4u;
        cp16(d0 + off1,                  Ah_g + asrc);
        cp16(d0 + off2,                  Ah_g + asrc + (size_t)64 * Kw);
        cp16(d0 + 128 * SSTR * 4 + off1, Al_g + asrc);
        cp16(d0 + 128 * SSTR * 4 + off2, Al_g + asrc + (size_t)64 * Kw);
        cp16(d0 + 256 * SSTR * 4 + off1, Bh_g + bsrc);
        cp16(d0 + 256 * SSTR * 4 + off2, Bh_g + bsrc + (size_t)64 * Kw);
        cp16(d0 + 384 * SSTR * 4 + off1, Bl_g + bsrc);
        cp16(d0 + 384 * SSTR * 4 + off2, Bl_g + bsrc + (size_t)64 * Kw);
    };

    float acc[4][4][4];
#pragma unroll
    for (int i = 0; i < 4; i++)
#pragma unroll
        for (int j = 0; j < 4; j++)
#pragma unroll
            for (int q = 0; q < 4; q++) acc[i][j][q] = 0.f;

    load_chunk(0, 0);
    cp_commit();

    for (int c = 0; c < KCH; c++) {
        const int buf = c & 1;
        if (c + 1 < KCH) { load_chunk(c + 1, buf ^ 1); cp_commit(); }
        // fused mask generation (overlaps in-flight copies)
        if (mw_stride) {
            const uint32_t w = mw_start + gid + (uint32_t)c * mw_stride;
            if (w < mw_end) g_mask[w] = mask_word(w);
        }
        if (c + 1 < KCH) cp_wait<1>(); else cp_wait<0>();
        __syncthreads();

        const uint32_t* Ah = smem + buf * BUFW;
        const uint32_t* Al = Ah + 128 * SSTR;
        const uint32_t* Bh = Ah + 256 * SSTR;
        const uint32_t* Bl = Ah + 384 * SSTR;

#pragma unroll
        for (int ks = 0; ks < 2; ks++) {
            uint32_t ah[4][4], al[4][4];
#pragma unroll
            for (int mt = 0; mt < 4; mt++) {
                const int r  = wy * 64 + mt * 16 + gq;
                const int cw = ks * 8 + gt;
                ah[mt][0] = Ah[r * SSTR + cw];
                ah[mt][1] = Ah[(r + 8) * SSTR + cw];
                ah[mt][2] = Ah[r * SSTR + cw + 4];
                ah[mt][3] = Ah[(r + 8) * SSTR + cw + 4];
                al[mt][0] = Al[r * SSTR + cw];
                al[mt][1] = Al[(r + 8) * SSTR + cw];
                al[mt][2] = Al[r * SSTR + cw + 4];
                al[mt][3] = Al[(r + 8) * SSTR + cw + 4];
            }
#pragma unroll
            for (int nt = 0; nt < 4; nt++) {
                const int n  = wx * 32 + nt * 8 + gq;
                const int kw = ks * 8 + gt;
                uint32_t bh[2], bl[2];
                bh[0] = Bh[n * SSTR + kw];
                bh[1] = Bh[n * SSTR + kw + 4];
                bl[0] = Bl[n * SSTR + kw];
                bl[1] = Bl[n * SSTR + kw + 4];
#pragma unroll
                for (int mt = 0; mt < 4; mt++) {
                    mma16816(acc[mt][nt], ah[mt], bh);
                    mma16816(acc[mt][nt], ah[mt], bl);
                    mma16816(acc[mt][nt], al[mt], bh);
                }
            }
        }
        __syncthreads();
    }

#pragma unroll
    for (int mt = 0; mt < 4; mt++) {
        const int r0 = m0 + wy * 64 + mt * 16 + gq;
#pragma unroll
        for (int nt = 0; nt < 4; nt++) {
            const int col = n0 + wx * 32 + nt * 8 + gt * 2;
            float bx = 0.f, by = 0.f;
            if (BIAS) { bx = bias[col]; by = bias[col + 1]; }
            *reinterpret_cast<float2*>(C + (size_t)r0 * N + col) =
                make_float2(acc[mt][nt][0] + bx, acc[mt][nt][1] + by);
            *reinterpret_cast<float2*>(C + (size_t)(r0 + 8) * N + col) =
                make_float2(acc[mt][nt][2] + bx, acc[mt][nt][3] + by);
        }
    }
}

// ===========================================================================
//  prep: split Q (scaled) / K head-major; transpose+split V
// ===========================================================================
__global__ __launch_bounds__(256) void prep_kernel()
{
    __shared__ float vs[64 * 100];
    const int nt = blockIdx.x, bh = blockIdx.y;
    const int b = bh >> 3, h = bh & 7;
    const int tid = threadIdx.x;
    const int n0 = nt * 64;

#pragma unroll
    for (int p = 0; p < 6; p++) {
        const int idx = tid + p * 256;
        const int row = idx / 24, c4 = idx % 24;
        const size_t grow = (size_t)(b * 1024 + n0 + row);
        float4 qv = *reinterpret_cast<const float4*>(g_q + grow * 768 + h * 96 + c4 * 4);
        uint32_t h01, l01, h23, l23;
        split2(qv.x * QSCALE, qv.y * QSCALE, h01, l01);
        split2(qv.z * QSCALE, qv.w * QSCALE, h23, l23);
        const size_t w = (size_t)(bh * 1024 + n0 + row) * 48 + c4 * 2;
        *reinterpret_cast<uint2*>(g_qh + w) = make_uint2(h01, h23);
        *reinterpret_cast<uint2*>(g_ql + w) = make_uint2(l01, l23);
        const float* kg = g_kv + grow * 1536 + h * 96 + c4 * 4;
        float4 kv = *reinterpret_cast<const float4*>(kg);
        split2(kv.x, kv.y, h01, l01);
        split2(kv.z, kv.w, h23, l23);
        *reinterpret_cast<uint2*>(g_kh + w) = make_uint2(h01, h23);
        *reinterpret_cast<uint2*>(g_kl + w) = make_uint2(l01, l23);
        float4 vv = *reinterpret_cast<const float4*>(kg + 768);
        *reinterpret_cast<float4*>(&vs[row * 100 + c4 * 4]) = vv;
    }
    __syncthreads();
#pragma unroll
    for (int p = 0; p < 12; p++) {
        const int idx = tid + p * 256;
        const int d = idx >> 5, nw = idx & 31;
        float v0 = vs[(2 * nw) * 100 + d];
        float v1 = vs[(2 * nw + 1) * 100 + d];
        uint32_t hh, ll;
        split2(v0, v1, hh, ll);
        const size_t w = (size_t)(bh * 96 + d) * 512 + nt * 32 + nw;
        g_vth[w] = hh; g_vtl[w] = ll;
    }
}

// ===========================================================================
//  fused attention. grid (8 qtiles of 128, 64 bh), 256 thr.
// ===========================================================================
constexpr int QSTR = 52;
constexpr int VSTR = 36;

DEV_INLINE void qk_mma(const uint32_t* Qh, const uint32_t* Ql,
                       const uint32_t* Kh, const uint32_t* Kl,
                       int rowb, int gq, int gt, float (*sacc)[4])
{
#pragma unroll
    for (int i = 0; i < 8; i++)
#pragma unroll
        for (int j = 0; j < 4; j++) sacc[i][j] = 0.f;
#pragma unroll
    for (int ks = 0; ks < 6; ks++) {
        const int cw = ks * 8 + gt;
        const int ra = (rowb + gq) * QSTR + cw;
        uint32_t ah[4], al[4];
        ah[0] = Qh[ra];            ah[1] = Qh[ra + 8 * QSTR];
        ah[2] = Qh[ra + 4];        ah[3] = Qh[ra + 8 * QSTR + 4];
        al[0] = Ql[ra];            al[1] = Ql[ra + 8 * QSTR];
        al[2] = Ql[ra + 4];        al[3] = Ql[ra + 8 * QSTR + 4];
#pragma unroll
        for (int nt = 0; nt < 8; nt++) {
            const int nb = (nt * 8 + gq) * QSTR + cw;
            uint32_t bh2[2] = {Kh[nb], Kh[nb + 4]};
            uint32_t bl2[2] = {Kl[nb], Kl[nb + 4]};
            mma16816(sacc[nt], ah, bh2);
            mma16816(sacc[nt], ah, bl2);
            mma16816(sacc[nt], al, bh2);
        }
    }
}

DEV_INLINE void qk_mma_hi(const uint32_t* Qh, const uint32_t* Kh,
                          int rowb, int gq, int gt, float (*sacc)[4])
{
#pragma unroll
    for (int i = 0; i < 8; i++)
#pragma unroll
        for (int j = 0; j < 4; j++) sacc[i][j] = 0.f;
#pragma unroll
    for (int ks = 0; ks < 6; ks++) {
        const int cw = ks * 8 + gt;
        const int ra = (rowb + gq) * QSTR + cw;
        uint32_t ah[4];
        ah[0] = Qh[ra];            ah[1] = Qh[ra + 8 * QSTR];
        ah[2] = Qh[ra + 4];        ah[3] = Qh[ra + 8 * QSTR + 4];
#pragma unroll
        for (int nt = 0; nt < 8; nt++) {
            const int nb = (nt * 8 + gq) * QSTR + cw;
            uint32_t bh2[2] = {Kh[nb], Kh[nb + 4]};
            mma16816(sacc[nt], ah, bh2);
        }
    }
}

DEV_INLINE void online_upd(float& m, float& z, float s) {
    float nm = fmaxf(m, s);
    z = z * __expf(m - nm) + __expf(s - nm);
    m = nm;
}
DEV_INLINE void comb_mz(float& m, float& z, int d) {
    float mo = __shfl_xor_sync(0xffffffffu, m, d);
    float zo = __shfl_xor_sync(0xffffffffu, z, d);
    float nm = fmaxf(m, mo);
    z = z * __expf(m - nm) + zo * __expf(mo - nm);
    m = nm;
}

__global__ __launch_bounds__(256, 2) void attn_mma()
{
    extern __shared__ uint32_t smw[];
    uint32_t* Qh = smw;
    uint32_t* Ql = Qh + 128 * QSTR;
    uint32_t* Kh = Ql + 128 * QSTR;
    uint32_t* Kl = Kh + 64 * QSTR;
    uint32_t* Vh = Kl + 64 * QSTR;
    uint32_t* Vl = Vh + 96 * VSTR;

    const int qt = blockIdx.x, bh = blockIdx.y;
    const int b = bh >> 3, h = bh & 7;
    const int tid = threadIdx.x, lane = tid & 31, wid = tid >> 5;
    const int gq = lane >> 2, gt = lane & 3;
    const int rowb = wid * 16;

    {
        const uint4* qh4 = reinterpret_cast<const uint4*>(g_qh + (size_t)(bh * 1024 + qt * 128) * 48);
        const uint4* ql4 = reinterpret_cast<const uint4*>(g_ql + (size_t)(bh * 1024 + qt * 128) * 48);
#pragma unroll
        for (int p = 0; p < 6; p++) {
            const int idx = tid + p * 256;
            const int row = idx / 12, s = idx % 12;
            *reinterpret_cast<uint4*>(&Qh[row * QSTR + s * 4]) = qh4[row * 12 + s];
            *reinterpret_cast<uint4*>(&Ql[row * QSTR + s * 4]) = ql4[row * 12 + s];
        }
    }

    float m1[2] = {-1e30f, -1e30f}, z1[2] = {0.f, 0.f};
    float m2[2] = {-1e30f, -1e30f}, z2[2] = {0.f, 0.f};
    float sacc[8][4];

    // ---- PASS A: stats (hi-only) ----
    for (int c = 0; c < 16; c++) {
        __syncthreads();
        {
            const uint4* kh4 = reinterpret_cast<const uint4*>(g_kh + (size_t)(bh * 1024 + c * 64) * 48);
#pragma unroll
            for (int p = 0; p < 3; p++) {
                const int idx = tid + p * 256;
                const int row = idx / 12, s = idx % 12;
                *reinterpret_cast<uint4*>(&Kh[row * QSTR + s * 4]) = kh4[row * 12 + s];
            }
        }
        __syncthreads();
        qk_mma_hi(Qh, Kh, rowb, gq, gt, sacc);

        if (c == 0) {
#pragma unroll
            for (int nt = 0; nt < 8; nt++)
#pragma unroll
                for (int v = 0; v < 4; v++) {
                    const int col = nt * 8 + gt * 2 + (v & 1);
                    const int r = v >> 1;
                    if (col < 20) online_upd(m1[r], z1[r], sacc[nt][v]);
                    else          online_upd(m2[r], z2[r], sacc[nt][v]);
                }
        } else {
#pragma unroll
            for (int r = 0; r < 2; r++) {
                float lm = -1e30f;
#pragma unroll
                for (int nt = 0; nt < 8; nt++)
                    lm = fmaxf(lm, fmaxf(sacc[nt][r * 2], sacc[nt][r * 2 + 1]));
                const float nm = fmaxf(m2[r], lm);
                float zs = 0.f;
#pragma unroll
                for (int nt = 0; nt < 8; nt++)
                    zs += __expf(sacc[nt][r * 2] - nm) + __expf(sacc[nt][r * 2 + 1] - nm);
                z2[r] = z2[r] * __expf(m2[r] - nm) + zs;
                m2[r] = nm;
            }
        }
    }
#pragma unroll
    for (int r = 0; r < 2; r++) {
        comb_mz(m1[r], z1[r], 1); comb_mz(m1[r], z1[r], 2);
        comb_mz(m2[r], z2[r], 1); comb_mz(m2[r], z2[r], 2);
    }
    const float rz1[2] = {1.f / z1[0], 1.f / z1[1]};
    const float rz2[2] = {1.f / z2[0], 1.f / z2[1]};

    // ---- PASS B ----
    float vacc[12][4];
#pragma unroll
    for (int i = 0; i < 12; i++)
#pragma unroll
        for (int j = 0; j < 4; j++) vacc[i][j] = 0.f;
    float zf[2] = {0.f, 0.f};
    const int q0 = qt * 128 + rowb + gq;
    const uint32_t* mrow = g_mask + ((size_t)(bh << 10) + q0) * 32;

    for (int c = 0; c < 16; c++) {
        __syncthreads();
        {
            const uint4* kh4 = reinterpret_cast<const uint4*>(g_kh + (size_t)(bh * 1024 + c * 64) * 48);
            const uint4* kl4 = reinterpret_cast<const uint4*>(g_kl + (size_t)(bh * 1024 + c * 64) * 48);
#pragma unroll
            for (int p = 0; p < 3; p++) {
                const int idx = tid + p * 256;
                const int row = idx / 12, s = idx % 12;
                *reinterpret_cast<uint4*>(&Kh[row * QSTR + s * 4]) = kh4[row * 12 + s];
                *reinterpret_cast<uint4*>(&Kl[row * QSTR + s * 4]) = kl4[row * 12 + s];
            }
            const uint4* vh4 = reinterpret_cast<const uint4*>(g_vth + (size_t)(bh * 96) * 512);
            const uint4* vl4 = reinterpret_cast<const uint4*>(g_vtl + (size_t)(bh * 96) * 512);
#pragma unroll
            for (int p = 0; p < 3; p++) {
                const int idx = tid + p * 256;
                const int row = idx >> 3, s = idx & 7;
                *reinterpret_cast<uint4*>(&Vh[row * VSTR + s * 4]) = vh4[row * 128 + c * 8 + s];
                *reinterpret_cast<uint4*>(&Vl[row * VSTR + s * 4]) = vl4[row * 128 + c * 8 + s];
            }
        }
        __syncthreads();
        qk_mma(Qh, Ql, Kh, Kl, rowb, gq, gt, sacc);

        const uint32_t mw0 = mrow[c * 2];
        const uint32_t mw1 = mrow[c * 2 + 1];
        const uint32_t mw2 = mrow[8 * 32 + c * 2];
        const uint32_t mw3 = mrow[8 * 32 + c * 2 + 1];

#pragma unroll
        for (int ks = 0; ks < 4; ks++) {
            uint32_t pah[4], pal[4];
#pragma unroll
            for (int half = 0; half < 2; half++) {
                const int nt = 2 * ks + half;
                float e[4];
#pragma unroll
                for (int v = 0; v < 4; v++) {
                    const int co = nt * 8 + gt * 2 + (v & 1);
                    const int r = v >> 1;
                    const bool cls = (c == 0) && (co < 20);
                    const float m  = cls ? m1[r] : m2[r];
                    const float rz = cls ? rz1[r] : rz2[r];
                    const float a  = __expf(sacc[nt][v] - m) * rz;
                    const uint32_t wsel = (nt < 4) ? (r ? mw2 : mw0) : (r ? mw3 : mw1);
                    const uint32_t keep = (wsel >> (co & 31)) & 1u;
                    const float ev = keep ? __expf(a - 1.f) : 0.f;
                    e[v] = ev;
                    zf[r] += ev;
                }
                uint32_t hh, ll;
                split2(e[0], e[1], hh, ll);
                pah[half * 2] = hh;     pal[half * 2] = ll;
                split2(e[2], e[3], hh, ll);
                pah[half * 2 + 1] = hh; pal[half * 2 + 1] = ll;
            }
            const int kw = ks * 8 + gt;
#pragma unroll
            for (int nt = 0; nt < 12; nt++) {
                const int nb = (nt * 8 + gq) * VSTR + kw;
                uint32_t bh2[2] = {Vh[nb], Vh[nb + 4]};
                uint32_t bl2[2] = {Vl[nb], Vl[nb + 4]};
                mma16816(vacc[nt], pah, bh2);
                mma16816(vacc[nt], pah, bl2);
                mma16816(vacc[nt], pal, bh2);
            }
        }
    }

#pragma unroll
    for (int r = 0; r < 2; r++) {
        zf[r] += __shfl_xor_sync(0xffffffffu, zf[r], 1);
        zf[r] += __shfl_xor_sync(0xffffffffu, zf[r], 2);
    }
    const float r0 = 1.f / zf[0], r1 = 1.f / zf[1];
    // write output directly as split bf16 words into the gemm-A buffers
    const size_t arow0 = (size_t)(b * 1024 + q0) * 384 + h * 48;
#pragma unroll
    for (int nt = 0; nt < 12; nt++) {
        const int wv = nt * 4 + gt;
        uint32_t hh, ll;
        split2(vacc[nt][0] * r0, vacc[nt][1] * r0, hh, ll);
        g_a1h[arow0 + wv] = hh; g_a1l[arow0 + wv] = ll;
        split2(vacc[nt][2] * r1, vacc[nt][3] * r1, hh, ll);
        g_a1h[arow0 + 8 * 384 + wv] = hh; g_a1l[arow0 + 8 * 384 + wv] = ll;
    }
}

// ---------------------------------------------------------------------------
extern "C" void kernel_launch(void* const* d_in, const int* in_sizes, int n_in,
                              void* d_out, int out_size)
{
    const float* input_query = (const float*)d_in[0];
    const float* input_key   = (const float*)d_in[1];
    const float* Wq          = (const float*)d_in[2];
    const float* Wkv         = (const float*)d_in[3];
    // d_in[4] = Wcls  -- provably unused
    const float* Wproj       = (const float*)d_in[5];
    const float* bproj       = (const float*)d_in[6];
    float* out = (float*)d_out;

    float *qp, *kvp;
    cudaGetSymbolAddress((void**)&qp,  g_q);
    cudaGetSymbolAddress((void**)&kvp, g_kv);
    uint32_t *a1h, *a1l, *a2h, *a2l, *wqh, *wql, *wkvh, *wkvl, *wph, *wpl;
    cudaGetSymbolAddress((void**)&a1h, g_a1h);
    cudaGetSymbolAddress((void**)&a1l, g_a1l);
    cudaGetSymbolAddress((void**)&a2h, g_a2h);
    cudaGetSymbolAddress((void**)&a2l, g_a2l);
    cudaGetSymbolAddress((void**)&wqh, g_wqh);
    cudaGetSymbolAddress((void**)&wql, g_wql);
    cudaGetSymbolAddress((void**)&wkvh, g_wkvh);
    cudaGetSymbolAddress((void**)&wkvl, g_wkvl);
    cudaGetSymbolAddress((void**)&wph, g_wph);
    cudaGetSymbolAddress((void**)&wpl, g_wpl);

    const int gemm_smem = 2 * BUFW * 4;   // 81920 B
    cudaFuncSetAttribute(gemm_v2<false>, cudaFuncAttributeMaxDynamicSharedMemorySize, gemm_smem);
    cudaFuncSetAttribute(gemm_v2<true>,  cudaFuncAttributeMaxDynamicSharedMemorySize, gemm_smem);
    const int attn_smem = (128 * QSTR * 2 + 64 * QSTR * 2 + 96 * VSTR * 2) * 4;
    cudaFuncSetAttribute(attn_mma, cudaFuncAttributeMaxDynamicSharedMemorySize, attn_smem);

    // operand splits
    rowsplit<<<6144, 256>>>(input_query, a1h, a1l, 8192 * 384);
    rowsplit<<<6144, 256>>>(input_key,   a2h, a2l, 8192 * 384);
    wsplit_t<<<dim3(24, 24), 256>>>(Wq,    wqh,  wql,  768, 768);
    wsplit_t<<<dim3(48, 24), 256>>>(Wkv,   wkvh, wkvl, 768, 1536);
    wsplit_t<<<dim3(24, 24), 256>>>(Wproj, wph,  wpl,  768, 768);

    // q = input_query @ Wq   (+ mask words [0, 1048576), stride = grid threads)
    gemm_v2<false><<<dim3(6, 64), 256, gemm_smem>>>(
        a1h, a1l, wqh, wql, nullptr, qp, 8192, 768, 768,
        0u, 1048576u, 98304u);
    // kv = input_key @ Wkv   (+ mask words [1048576, 2097152))
    gemm_v2<false><<<dim3(12, 64), 256, gemm_smem>>>(
        a2h, a2l, wkvh, wkvl, nullptr, kvp, 8192, 1536, 768,
        1048576u, 2097152u, 196608u);
    prep_kernel<<<dim3(16, 64), 256>>>();
    attn_mma<<<dim3(8, 64), 256, attn_smem>>>();   // writes a1h/a1l
    // out = attn_out @ Wproj + b
    gemm_v2<true><<<dim3(6, 64), 256, gemm_smem>>>(
        a1h, a1l, wph, wpl, bproj, out, 8192, 768, 768,
        0u, 0u, 0u);
}

// round 8
// speedup vs baseline: 1.3902x; 1.3902x over previous
#include <cuda_runtime.h>
#include <cuda_bf16.h>
#include <cstdint>

// ---------------------------------------------------------------------------
// CrossAttention: B=8, Nt=1024, N=1024, D=768, H=8, HD=96, CLS=20, L=1044
// Round-6 base (best: 984.6us) + ONE change: weights pre-transposed/pre-split
// (k-contiguous bf16 hi/lo), GEMM B-loads now coalesced uint4, no in-loop
// B split2. Everything else identical to round 6.
// ---------------------------------------------------------------------------

#define DEV_INLINE __device__ __forceinline__

constexpr int   Bsz  = 8;
constexpr int   NtQ  = 1024;
constexpr int   Dm   = 768;
constexpr float QSCALE = 0.10206207261596577f;   // 96^-0.5

// ---------------- scratch (static device globals; no allocation) -----------
__device__ float    g_q  [Bsz * NtQ * Dm];          // 25 MB
__device__ float    g_kv [Bsz * NtQ * 2 * Dm];      // 50 MB
__device__ float    g_ao [Bsz * NtQ * Dm];          // 25 MB
// pre-split transposed weights (bf16x2 words, k-contiguous  [N][K/2])
__device__ uint32_t g_wqh [ 768 * 384], g_wql [ 768 * 384];
__device__ uint32_t g_wkvh[1536 * 384], g_wkvl[1536 * 384];
__device__ uint32_t g_wph [ 768 * 384], g_wpl [ 768 * 384];
// attention operands (head-major)
__device__ uint32_t g_qh [64 * 1024 * 48];
__device__ uint32_t g_ql [64 * 1024 * 48];
__device__ uint32_t g_kh [64 * 1024 * 48];
__device__ uint32_t g_kl [64 * 1024 * 48];
__device__ uint32_t g_vth[64 * 96 * 512];
__device__ uint32_t g_vtl[64 * 96 * 512];
__device__ uint32_t g_mask[64 * 1024 * 32];         // 8.4 MB keep-bitmask

// ---------------------------------------------------------------------------
DEV_INLINE void split2(float x, float y, uint32_t& hi, uint32_t& lo) {
    __nv_bfloat162 h = __floats2bfloat162_rn(x, y);
    float hx = __bfloat162float(h.x), hy = __bfloat162float(h.y);
    __nv_bfloat162 l = __floats2bfloat162_rn(x - hx, y - hy);
    hi = *reinterpret_cast<uint32_t*>(&h);
    lo = *reinterpret_cast<uint32_t*>(&l);
}

DEV_INLINE void mma16816(float* d, const uint32_t* a, const uint32_t* b) {
    asm volatile(
        "mma.sync.aligned.m16n8k16.row.col.f32.bf16.bf16.f32 "
        "{%0,%1,%2,%3}, {%4,%5,%6,%7}, {%8,%9}, {%0,%1,%2,%3};"
        : "+f"(d[0]), "+f"(d[1]), "+f"(d[2]), "+f"(d[3])
        : "r"(a[0]), "r"(a[1]), "r"(a[2]), "r"(a[3]), "r"(b[0]), "r"(b[1]));
}

DEV_INLINE uint32_t rotl32(uint32_t x, int d) { return __funnelshift_l(x, x, d); }

// JAX threefry2x32, key (0,42), partitionable: counter (0, fi), out = x0^x1
DEV_INLINE uint32_t tf_bits(uint32_t fi) {
    const uint32_t ks1 = 42u, ks2 = 0x1BD11BF0u;
    uint32_t x0 = 0u, x1 = fi + ks1;
    x0 += x1; x1 = rotl32(x1, 13); x1 ^= x0;
    x0 += x1; x1 = rotl32(x1, 15); x1 ^= x0;
    x0 += x1; x1 = rotl32(x1, 26); x1 ^= x0;
    x0 += x1; x1 = rotl32(x1,  6); x1 ^= x0;
    x0 += ks1; x1 += ks2 + 1u;
    x0 += x1; x1 = rotl32(x1, 17); x1 ^= x0;
    x0 += x1; x1 = rotl32(x1, 29); x1 ^= x0;
    x0 += x1; x1 = rotl32(x1, 16); x1 ^= x0;
    x0 += x1; x1 = rotl32(x1, 24); x1 ^= x0;
    x0 += ks2; x1 += 2u;
    x0 += x1; x1 = rotl32(x1, 13); x1 ^= x0;
    x0 += x1; x1 = rotl32(x1, 15); x1 ^= x0;
    x0 += x1; x1 = rotl32(x1, 26); x1 ^= x0;
    x0 += x1; x1 = rotl32(x1,  6); x1 ^= x0;
    x1 += ks1 + 3u;
    x0 += x1; x1 = rotl32(x1, 17); x1 ^= x0;
    x0 += x1; x1 = rotl32(x1, 29); x1 ^= x0;
    x0 += x1; x1 = rotl32(x1, 16); x1 ^= x0;
    x0 += x1; x1 = rotl32(x1, 24); x1 ^= x0;
    x0 += ks1; x1 += ks2 + 4u;
    x0 += x1; x1 = rotl32(x1, 13); x1 ^= x0;
    x0 += x1; x1 = rotl32(x1, 15); x1 ^= x0;
    x0 += x1; x1 = rotl32(x1, 26); x1 ^= x0;
    x0 += x1; x1 = rotl32(x1,  6); x1 ^= x0;
    x0 += ks2; x1 += 5u;
    return x0 ^ x1;
}

// w = (bh*1024 + q)*32 + wi ; bit j (keep=1) for col wi*32+j
DEV_INLINE uint32_t mask_word(uint32_t w) {
    const uint32_t bh = w >> 15;
    const uint32_t rest = w & 32767u;
    const uint32_t q = rest >> 5, wi = rest & 31u;
    const uint32_t fi0 = (bh * 1044u + 20u + q) * 1024u + wi * 32u;
    uint32_t bits = 0u;
#pragma unroll 4
    for (int j = 0; j < 32; j++) {
        uint32_t b = tf_bits(fi0 + (uint32_t)j);
        bits |= ((b >> 9) >= 2516583u ? 1u : 0u) << j;
    }
    return bits;
}

// ===========================================================================
//  weight transpose+split: W [K][N] row-major -> hi/lo [N][K/2] k-contiguous
// ===========================================================================
__global__ __launch_bounds__(256) void wsplit_t(
    const float* __restrict__ W, uint32_t* __restrict__ dh,
    uint32_t* __restrict__ dl, int K, int N)
{
    __shared__ float s[32][33];
    const int tid = threadIdx.x;
    const int kt = blockIdx.y, nt = blockIdx.x;
    const int kl = tid >> 5, nl = tid & 31;
#pragma unroll
    for (int i = 0; i < 4; i++)
        s[kl + i * 8][nl] = W[(size_t)(kt * 32 + kl + i * 8) * N + nt * 32 + nl];
    __syncthreads();
    const int n2 = tid >> 3, q = tid & 7;
    const int Kw = K >> 1;
    uint32_t h, l;
    split2(s[2 * q][n2], s[2 * q + 1][n2], h, l);
    size_t o = (size_t)(nt * 32 + n2) * Kw + kt * 16 + q;
    dh[o] = h; dl[o] = l;
    split2(s[2 * q + 16][n2], s[2 * q + 17][n2], h, l);
    dh[o + 8] = h; dl[o + 8] = l;
}

// ===========================================================================
//  mma.sync GEMM (round-6 base): A fp32 inline-split; B pre-split coalesced.
//  C[M,N] = A[M,K] @ Bt[N,K]^T (+bias).  CTA 128x128, K-chunk 32.
// ===========================================================================
constexpr int SSTR = 20;

template<bool BIAS>
__global__ __launch_bounds__(256, 2) void mma_gemm(
    const float* __restrict__ A,
    const uint32_t* __restrict__ Bh_g, const uint32_t* __restrict__ Bl_g,
    const float* __restrict__ bias, float* __restrict__ C,
    int M, int N, int K,
    uint32_t mw_start, uint32_t mw_end, uint32_t mw_stride)
{
    __shared__ uint32_t Ah[128 * SSTR];
    __shared__ uint32_t Al[128 * SSTR];
    __shared__ uint32_t Bh[128 * SSTR];
    __shared__ uint32_t Bl[128 * SSTR];

    const int tid  = threadIdx.x;
    const int lane = tid & 31;
    const int wid  = tid >> 5;
    const int wy   = wid >> 2;
    const int wx   = wid & 3;

    const int m0 = blockIdx.y * 128;
    const int n0 = blockIdx.x * 128;
    const int Kw = K >> 1;
    const uint32_t gid =
        ((uint32_t)blockIdx.y * gridDim.x + blockIdx.x) * 256u + (uint32_t)tid;

    float acc[4][4][4];
#pragma unroll
    for (int i = 0; i < 4; i++)
#pragma unroll
        for (int j = 0; j < 4; j++)
#pragma unroll
            for (int q = 0; q < 4; q++) acc[i][j][q] = 0.f;

    const int gq = lane >> 2;
    const int gt = lane & 3;

    for (int kc = 0; kc < K; kc += 32) {
        __syncthreads();
        // ---- A chunk [128m x 32k] : fp32 float4, inline split (coalesced) ----
#pragma unroll
        for (int p = 0; p < 4; p++) {
            const int idx = tid + p * 256;
            const int row = idx >> 3, c4 = idx & 7;
            float4 v = *reinterpret_cast<const float4*>(
                A + (size_t)(m0 + row) * K + kc + c4 * 4);
            uint32_t h01, l01, h23, l23;
            split2(v.x, v.y, h01, l01);
            split2(v.z, v.w, h23, l23);
            const int w = row * SSTR + c4 * 2;
            Ah[w] = h01; Ah[w + 1] = h23;
            Al[w] = l01; Al[w + 1] = l23;
        }
        // ---- B chunk: pre-split hi/lo, coalesced uint4 (16 words/row) ----
#pragma unroll
        for (int p = 0; p < 2; p++) {
            const int idx = tid + p * 256;          // 512 uint4 per array
            const int row = idx >> 2, q = idx & 3;
            const size_t src = (size_t)(n0 + row) * Kw + (kc >> 1) + q * 4;
            *reinterpret_cast<uint4*>(&Bh[row * SSTR + q * 4]) =
                *reinterpret_cast<const uint4*>(Bh_g + src);
            *reinterpret_cast<uint4*>(&Bl[row * SSTR + q * 4]) =
                *reinterpret_cast<const uint4*>(Bl_g + src);
        }
        // ---- fused mask generation (fills stall slots) ----
        if (mw_stride) {
            const uint32_t w = mw_start + gid + (uint32_t)(kc >> 5) * mw_stride;
            if (w < mw_end) g_mask[w] = mask_word(w);
        }
        __syncthreads();

#pragma unroll
        for (int ks = 0; ks < 2; ks++) {
            uint32_t ah[4][4], al[4][4];
#pragma unroll
            for (int mt = 0; mt < 4; mt++) {
                const int r  = wy * 64 + mt * 16 + gq;
                const int cw = ks * 8 + gt;
                ah[mt][0] = Ah[r * SSTR + cw];
                ah[mt][1] = Ah[(r + 8) * SSTR + cw];
                ah[mt][2] = Ah[r * SSTR + cw + 4];
                ah[mt][3] = Ah[(r + 8) * SSTR + cw + 4];
                al[mt][0] = Al[r * SSTR + cw];
                al[mt][1] = Al[(r + 8) * SSTR + cw];
                al[mt][2] = Al[r * SSTR + cw + 4];
                al[mt][3] = Al[(r + 8) * SSTR + cw + 4];
            }
#pragma unroll
            for (int nt = 0; nt < 4; nt++) {
                const int n  = wx * 32 + nt * 8 + gq;
                const int kw = ks * 8 + gt;
                uint32_t bh[2], bl[2];
                bh[0] = Bh[n * SSTR + kw];
                bh[1] = Bh[n * SSTR + kw + 4];
                bl[0] = Bl[n * SSTR + kw];
                bl[1] = Bl[n * SSTR + kw + 4];
#pragma unroll
                for (int mt = 0; mt < 4; mt++) {
                    mma16816(acc[mt][nt], ah[mt], bh);
                    mma16816(acc[mt][nt], ah[mt], bl);
                    mma16816(acc[mt][nt], al[mt], bh);
                }
            }
        }
    }

#pragma unroll
    for (int mt = 0; mt < 4; mt++) {
        const int r0 = m0 + wy * 64 + mt * 16 + gq;
#pragma unroll
        for (int nt = 0; nt < 4; nt++) {
            const int col = n0 + wx * 32 + nt * 8 + gt * 2;
            float bx = 0.f, by = 0.f;
            if (BIAS) { bx = bias[col]; by = bias[col + 1]; }
            *reinterpret_cast<float2*>(C + (size_t)r0 * N + col) =
                make_float2(acc[mt][nt][0] + bx, acc[mt][nt][1] + by);
            *reinterpret_cast<float2*>(C + (size_t)(r0 + 8) * N + col) =
                make_float2(acc[mt][nt][2] + bx, acc[mt][nt][3] + by);
        }
    }
}

// ===========================================================================
//  prep: split Q (scaled) / K head-major; transpose+split V
// ===========================================================================
__global__ __launch_bounds__(256) void prep_kernel()
{
    __shared__ float vs[64 * 100];
    const int nt = blockIdx.x, bh = blockIdx.y;
    const int b = bh >> 3, h = bh & 7;
    const int tid = threadIdx.x;
    const int n0 = nt * 64;

#pragma unroll
    for (int p = 0; p < 6; p++) {
        const int idx = tid + p * 256;
        const int row = idx / 24, c4 = idx % 24;
        const size_t grow = (size_t)(b * 1024 + n0 + row);
        float4 qv = *reinterpret_cast<const float4*>(g_q + grow * 768 + h * 96 + c4 * 4);
        uint32_t h01, l01, h23, l23;
        split2(qv.x * QSCALE, qv.y * QSCALE, h01, l01);
        split2(qv.z * QSCALE, qv.w * QSCALE, h23, l23);
        const size_t w = (size_t)(bh * 1024 + n0 + row) * 48 + c4 * 2;
        *reinterpret_cast<uint2*>(g_qh + w) = make_uint2(h01, h23);
        *reinterpret_cast<uint2*>(g_ql + w) = make_uint2(l01, l23);
        const float* kg = g_kv + grow * 1536 + h * 96 + c4 * 4;
        float4 kv = *reinterpret_cast<const float4*>(kg);
        split2(kv.x, kv.y, h01, l01);
        split2(kv.z, kv.w, h23, l23);
        *reinterpret_cast<uint2*>(g_kh + w) = make_uint2(h01, h23);
        *reinterpret_cast<uint2*>(g_kl + w) = make_uint2(l01, l23);
        float4 vv = *reinterpret_cast<const float4*>(kg + 768);
        *reinterpret_cast<float4*>(&vs[row * 100 + c4 * 4]) = vv;
    }
    __syncthreads();
#pragma unroll
    for (int p = 0; p < 12; p++) {
        const int idx = tid + p * 256;
        const int d = idx >> 5, nw = idx & 31;
        float v0 = vs[(2 * nw) * 100 + d];
        float v1 = vs[(2 * nw + 1) * 100 + d];
        uint32_t hh, ll;
        split2(v0, v1, hh, ll);
        const size_t w = (size_t)(bh * 96 + d) * 512 + nt * 32 + nw;
        g_vth[w] = hh; g_vtl[w] = ll;
    }
}

// ===========================================================================
//  fused attention (round-6, unchanged). grid (8 qtiles of 128, 64 bh).
// ===========================================================================
constexpr int QSTR = 52;
constexpr int VSTR = 36;

DEV_INLINE void qk_mma(const uint32_t* Qh, const uint32_t* Ql,
                       const uint32_t* Kh, const uint32_t* Kl,
                       int rowb, int gq, int gt, float (*sacc)[4])
{
#pragma unroll
    for (int i = 0; i < 8; i++)
#pragma unroll
        for (int j = 0; j < 4; j++) sacc[i][j] = 0.f;
#pragma unroll
    for (int ks = 0; ks < 6; ks++) {
        const int cw = ks * 8 + gt;
        const int ra = (rowb + gq) * QSTR + cw;
        uint32_t ah[4], al[4];
        ah[0] = Qh[ra];            ah[1] = Qh[ra + 8 * QSTR];
        ah[2] = Qh[ra + 4];        ah[3] = Qh[ra + 8 * QSTR + 4];
        al[0] = Ql[ra];            al[1] = Ql[ra + 8 * QSTR];
        al[2] = Ql[ra + 4];        al[3] = Ql[ra + 8 * QSTR + 4];
#pragma unroll
        for (int nt = 0; nt < 8; nt++) {
            const int nb = (nt * 8 + gq) * QSTR + cw;
            uint32_t bh2[2] = {Kh[nb], Kh[nb + 4]};
            uint32_t bl2[2] = {Kl[nb], Kl[nb + 4]};
            mma16816(sacc[nt], ah, bh2);
            mma16816(sacc[nt], ah, bl2);
            mma16816(sacc[nt], al, bh2);
        }
    }
}

DEV_INLINE void qk_mma_hi(const uint32_t* Qh, const uint32_t* Kh,
                          int rowb, int gq, int gt, float (*sacc)[4])
{
#pragma unroll
    for (int i = 0; i < 8; i++)
#pragma unroll
        for (int j = 0; j < 4; j++) sacc[i][j] = 0.f;
#pragma unroll
    for (int ks = 0; ks < 6; ks++) {
        const int cw = ks * 8 + gt;
        const int ra = (rowb + gq) * QSTR + cw;
        uint32_t ah[4];
        ah[0] = Qh[ra];            ah[1] = Qh[ra + 8 * QSTR];
        ah[2] = Qh[ra + 4];        ah[3] = Qh[ra + 8 * QSTR + 4];
#pragma unroll
        for (int nt = 0; nt < 8; nt++) {
            const int nb = (nt * 8 + gq) * QSTR + cw;
            uint32_t bh2[2] = {Kh[nb], Kh[nb + 4]};
            mma16816(sacc[nt], ah, bh2);
        }
    }
}

DEV_INLINE void online_upd(float& m, float& z, float s) {
    float nm = fmaxf(m, s);
    z = z * __expf(m - nm) + __expf(s - nm);
    m = nm;
}
DEV_INLINE void comb_mz(float& m, float& z, int d) {
    float mo = __shfl_xor_sync(0xffffffffu, m, d);
    float zo = __shfl_xor_sync(0xffffffffu, z, d);
    float nm = fmaxf(m, mo);
    z = z * __expf(m - nm) + zo * __expf(mo - nm);
    m = nm;
}

__global__ __launch_bounds__(256, 2) void attn_mma()
{
    extern __shared__ uint32_t smw[];
    uint32_t* Qh = smw;
    uint32_t* Ql = Qh + 128 * QSTR;
    uint32_t* Kh = Ql + 128 * QSTR;
    uint32_t* Kl = Kh + 64 * QSTR;
    uint32_t* Vh = Kl + 64 * QSTR;
    uint32_t* Vl = Vh + 96 * VSTR;

    const int qt = blockIdx.x, bh = blockIdx.y;
    const int b = bh >> 3, h = bh & 7;
    const int tid = threadIdx.x, lane = tid & 31, wid = tid >> 5;
    const int gq = lane >> 2, gt = lane & 3;
    const int rowb = wid * 16;

    {
        const uint4* qh4 = reinterpret_cast<const uint4*>(g_qh + (size_t)(bh * 1024 + qt * 128) * 48);
        const uint4* ql4 = reinterpret_cast<const uint4*>(g_ql + (size_t)(bh * 1024 + qt * 128) * 48);
#pragma unroll
        for (int p = 0; p < 6; p++) {
            const int idx = tid + p * 256;
            const int row = idx / 12, s = idx % 12;
            *reinterpret_cast<uint4*>(&Qh[row * QSTR + s * 4]) = qh4[row * 12 + s];
            *reinterpret_cast<uint4*>(&Ql[row * QSTR + s * 4]) = ql4[row * 12 + s];
        }
    }

    float m1[2] = {-1e30f, -1e30f}, z1[2] = {0.f, 0.f};
    float m2[2] = {-1e30f, -1e30f}, z2[2] = {0.f, 0.f};
    float sacc[8][4];

    // ---- PASS A: stats (hi-only) ----
    for (int c = 0; c < 16; c++) {
        __syncthreads();
        {
            const uint4* kh4 = reinterpret_cast<const uint4*>(g_kh + (size_t)(bh * 1024 + c * 64) * 48);
#pragma unroll
            for (int p = 0; p < 3; p++) {
                const int idx = tid + p * 256;
                const int row = idx / 12, s = idx % 12;
                *reinterpret_cast<uint4*>(&Kh[row * QSTR + s * 4]) = kh4[row * 12 + s];
            }
        }
        __syncthreads();
        qk_mma_hi(Qh, Kh, rowb, gq, gt, sacc);

        if (c == 0) {
#pragma unroll
            for (int nt = 0; nt < 8; nt++)
#pragma unroll
                for (int v = 0; v < 4; v++) {
                    const int col = nt * 8 + gt * 2 + (v & 1);
                    const int r = v >> 1;
                    if (col < 20) online_upd(m1[r], z1[r], sacc[nt][v]);
                    else          online_upd(m2[r], z2[r], sacc[nt][v]);
                }
        } else {
#pragma unroll
            for (int r = 0; r < 2; r++) {
                float lm = -1e30f;
#pragma unroll
                for (int nt = 0; nt < 8; nt++)
                    lm = fmaxf(lm, fmaxf(sacc[nt][r * 2], sacc[nt][r * 2 + 1]));
                const float nm = fmaxf(m2[r], lm);
                float zs = 0.f;
#pragma unroll
                for (int nt = 0; nt < 8; nt++)
                    zs += __expf(sacc[nt][r * 2] - nm) + __expf(sacc[nt][r * 2 + 1] - nm);
                z2[r] = z2[r] * __expf(m2[r] - nm) + zs;
                m2[r] = nm;
            }
        }
    }
#pragma unroll
    for (int r = 0; r < 2; r++) {
        comb_mz(m1[r], z1[r], 1); comb_mz(m1[r], z1[r], 2);
        comb_mz(m2[r], z2[r], 1); comb_mz(m2[r], z2[r], 2);
    }
    const float rz1[2] = {1.f / z1[0], 1.f / z1[1]};
    const float rz2[2] = {1.f / z2[0], 1.f / z2[1]};

    // ---- PASS B ----
    float vacc[12][4];
#pragma unroll
    for (int i = 0; i < 12; i++)
#pragma unroll
        for (int j = 0; j < 4; j++) vacc[i][j] = 0.f;
    float zf[2] = {0.f, 0.f};
    const int q0 = qt * 128 + rowb + gq;
    const uint32_t* mrow = g_mask + ((size_t)(bh << 10) + q0) * 32;

    for (int c = 0; c < 16; c++) {
        __syncthreads();
        {
            const uint4* kh4 = reinterpret_cast<const uint4*>(g_kh + (size_t)(bh * 1024 + c * 64) * 48);
            const uint4* kl4 = reinterpret_cast<const uint4*>(g_kl + (size_t)(bh * 1024 + c * 64) * 48);
#pragma unroll
            for (int p = 0; p < 3; p++) {
                const int idx = tid + p * 256;
                const int row = idx / 12, s = idx % 12;
                *reinterpret_cast<uint4*>(&Kh[row * QSTR + s * 4]) = kh4[row * 12 + s];
                *reinterpret_cast<uint4*>(&Kl[row * QSTR + s * 4]) = kl4[row * 12 + s];
            }
            const uint4* vh4 = reinterpret_cast<const uint4*>(g_vth + (size_t)(bh * 96) * 512);
            const uint4* vl4 = reinterpret_cast<const uint4*>(g_vtl + (size_t)(bh * 96) * 512);
#pragma unroll
            for (int p = 0; p < 3; p++) {
                const int idx = tid + p * 256;
                const int row = idx >> 3, s = idx & 7;
                *reinterpret_cast<uint4*>(&Vh[row * VSTR + s * 4]) = vh4[row * 128 + c * 8 + s];
                *reinterpret_cast<uint4*>(&Vl[row * VSTR + s * 4]) = vl4[row * 128 + c * 8 + s];
            }
        }
        __syncthreads();
        qk_mma(Qh, Ql, Kh, Kl, rowb, gq, gt, sacc);

        const uint32_t mw0 = mrow[c * 2];
        const uint32_t mw1 = mrow[c * 2 + 1];
        const uint32_t mw2 = mrow[8 * 32 + c * 2];
        const uint32_t mw3 = mrow[8 * 32 + c * 2 + 1];

#pragma unroll
        for (int ks = 0; ks < 4; ks++) {
            uint32_t pah[4], pal[4];
#pragma unroll
            for (int half = 0; half < 2; half++) {
                const int nt = 2 * ks + half;
                float e[4];
#pragma unroll
                for (int v = 0; v < 4; v++) {
                    const int co = nt * 8 + gt * 2 + (v & 1);
                    const int r = v >> 1;
                    const bool cls = (c == 0) && (co < 20);
                    const float m  = cls ? m1[r] : m2[r];
                    const float rz = cls ? rz1[r] : rz2[r];
                    const float a  = __expf(sacc[nt][v] - m) * rz;
                    const uint32_t wsel = (nt < 4) ? (r ? mw2 : mw0) : (r ? mw3 : mw1);
                    const uint32_t keep = (wsel >> (co & 31)) & 1u;
                    const float ev = keep ? __expf(a - 1.f) : 0.f;
                    e[v] = ev;
                    zf[r] += ev;
                }
                uint32_t hh, ll;
                split2(e[0], e[1], hh, ll);
                pah[half * 2] = hh;     pal[half * 2] = ll;
                split2(e[2], e[3], hh, ll);
                pah[half * 2 + 1] = hh; pal[half * 2 + 1] = ll;
            }
            const int kw = ks * 8 + gt;
#pragma unroll
            for (int nt = 0; nt < 12; nt++) {
                const int nb = (nt * 8 + gq) * VSTR + kw;
                uint32_t bh2[2] = {Vh[nb], Vh[nb + 4]};
                uint32_t bl2[2] = {Vl[nb], Vl[nb + 4]};
                mma16816(vacc[nt], pah, bh2);
                mma16816(vacc[nt], pah, bl2);
                mma16816(vacc[nt], pal, bh2);
            }
        }
    }

#pragma unroll
    for (int r = 0; r < 2; r++) {
        zf[r] += __shfl_xor_sync(0xffffffffu, zf[r], 1);
        zf[r] += __shfl_xor_sync(0xffffffffu, zf[r], 2);
    }
    const float r0 = 1.f / zf[0], r1 = 1.f / zf[1];
    float* og = g_ao + (size_t)(b * 1024 + q0) * 768 + h * 96;
#pragma unroll
    for (int nt = 0; nt < 12; nt++) {
        const int col = nt * 8 + gt * 2;
        *reinterpret_cast<float2*>(og + col) =
            make_float2(vacc[nt][0] * r0, vacc[nt][1] * r0);
        *reinterpret_cast<float2*>(og + 8 * 768 + col) =
            make_float2(vacc[nt][2] * r1, vacc[nt][3] * r1);
    }
}

// ---------------------------------------------------------------------------
extern "C" void kernel_launch(void* const* d_in, const int* in_sizes, int n_in,
                              void* d_out, int out_size)
{
    const float* input_query = (const float*)d_in[0];
    const float* input_key   = (const float*)d_in[1];
    const float* Wq          = (const float*)d_in[2];
    const float* Wkv         = (const float*)d_in[3];
    // d_in[4] = Wcls  -- provably unused
    const float* Wproj       = (const float*)d_in[5];
    const float* bproj       = (const float*)d_in[6];
    float* out = (float*)d_out;

    float *qp, *kvp, *aop;
    cudaGetSymbolAddress((void**)&qp,  g_q);
    cudaGetSymbolAddress((void**)&kvp, g_kv);
    cudaGetSymbolAddress((void**)&aop, g_ao);
    uint32_t *wqh, *wql, *wkvh, *wkvl, *wph, *wpl;
    cudaGetSymbolAddress((void**)&wqh,  g_wqh);
    cudaGetSymbolAddress((void**)&wql,  g_wql);
    cudaGetSymbolAddress((void**)&wkvh, g_wkvh);
    cudaGetSymbolAddress((void**)&wkvl, g_wkvl);
    cudaGetSymbolAddress((void**)&wph,  g_wph);
    cudaGetSymbolAddress((void**)&wpl,  g_wpl);

    const int attn_smem = (128 * QSTR * 2 + 64 * QSTR * 2 + 96 * VSTR * 2) * 4;
    cudaFuncSetAttribute(attn_mma, cudaFuncAttributeMaxDynamicSharedMemorySize, attn_smem);

    // weight transpose+split (measured ~7us each)
    wsplit_t<<<dim3(24, 24), 256>>>(Wq,    wqh,  wql,  768, 768);
    wsplit_t<<<dim3(48, 24), 256>>>(Wkv,   wkvh, wkvl, 768, 1536);
    wsplit_t<<<dim3(24, 24), 256>>>(Wproj, wph,  wpl,  768, 768);

    // q = input_query @ Wq   (+ mask words [0, 1048576))
    mma_gemm<false><<<dim3(6, 64), 256>>>(input_query, wqh, wql, nullptr, qp,
                                          8192, 768, 768,
                                          0u, 1048576u, 98304u);
    // kv = input_key @ Wkv   (+ mask words [1048576, 2097152))
    mma_gemm<false><<<dim3(12, 64), 256>>>(input_key, wkvh, wkvl, nullptr, kvp,
                                           8192, 1536, 768,
                                           1048576u, 2097152u, 196608u);
    prep_kernel<<<dim3(16, 64), 256>>>();
    attn_mma<<<dim3(8, 64), 256, attn_smem>>>();
    // out = attn_out @ Wproj + b
    mma_gemm<true><<<dim3(6, 64), 256>>>(aop, wph, wpl, bproj, out,
                                         8192, 768, 768,
                                         0u, 0u, 0u);
}